// round 13
// baseline (speedup 1.0000x reference)
#include <cuda_runtime.h>
#include <cuda_bf16.h>

#define N_WAVES 128
#define POLYN 12                 // top-POLYN waves by freq -> exact-reduction poly path
#define RAWN (N_WAVES - POLYN)   // 116 low/mid-freq waves -> raw-radian MUFU path
#define TPB 128
#define GRID_X (148 * 8)         // exactly 8 CTAs per SM, all resident in one wave

__device__ __forceinline__ float sinap(float a) {
    float r; asm("sin.approx.f32 %0, %1;" : "=f"(r) : "f"(a)); return r;
}

// sin(pi*d), d in [-0.5, 0.5]: degree-7 odd minimax (folded per-wave with A)
#define A1F  3.14158197f
#define A3F -5.16714000f
#define A5F  2.54189000f
#define A7F -0.55461700f
#define MAGF 12582912.f          // 1.5 * 2^23

__global__ void __launch_bounds__(TPB, 8)
wave_kernel(const float4* __restrict__ x4,   // 2 points per float4
            const float* __restrict__ freqs,
            const float* __restrict__ rots,
            const float* __restrict__ coeffs,
            float2* __restrict__ out2, int n) {
    // Slots [0, RAWN): raw-radian MUFU waves: swp = (gx,gy,ph,A) in radians.
    // Slots [RAWN,128): poly waves: swp = (gx,gy,ph,-) in HALF-CYCLES,
    //                   spoly = A-folded coeffs (A*A1, A*A3, A*A5, A*A7).
    __shared__ float sf[N_WAVES];
    __shared__ float4 swp[N_WAVES];
    __shared__ float4 spoly[POLYN];

    int w = threadIdx.x;
    float fw = 0.f;
    if (w < N_WAVES) { fw = freqs[w]; sf[w] = fw; }
    __syncthreads();

    if (w < N_WAVES) {
        // Deterministic rank (descending freq, tie-break by index).
        int rank = 0;
        for (int j = 0; j < N_WAVES; j++) {
            float fj = sf[j];
            rank += (fj > fw) || (fj == fw && j < w);
        }
        bool isPoly = (rank < POLYN);

        float r  = rots[w];
        float c0 = coeffs[2 * w];
        float c1 = coeffs[2 * w + 1];
        float sr, cr;
        sincosf(r, &sr, &cr);
        float A  = sqrtf(c0 * c0 + c1 * c1);
        float ph = atan2f(c1, c0);            // radians
        if (isPoly) {                          // half-cycle domain, A folded into coeffs
            swp[RAWN + rank] = make_float4(2.f * fw * cr, 2.f * fw * sr,
                                           ph * 0.3183098861837907f, 0.f);
            spoly[rank] = make_float4(A * A1F, A * A3F, A * A5F, A * A7F);
        } else {                               // raw radian domain
            const float two_pi = 6.283185307179586f;
            swp[rank - POLYN] = make_float4(two_pi * fw * cr, two_pi * fw * sr, ph, A);
        }
    }
    __syncthreads();

    unsigned pairsTotal = (unsigned)(n >> 1);       // float4 count
    const unsigned TH = GRID_X * TPB;               // total threads
    unsigned T = blockIdx.x * TPB + threadIdx.x;
    // Bresenham partition: exact, contiguous, per-SM balanced to ~0.1%.
    unsigned pStart = (unsigned)(((unsigned long long)T * pairsTotal) / TH);
    unsigned pEnd   = (unsigned)(((unsigned long long)(T + 1) * pairsTotal) / TH);

    for (unsigned p = pStart; p < pEnd; p++) {
        float4 a = x4[p];
        float x0 = a.x, y0 = a.y, x1 = a.z, y1 = a.w;
        float acc0 = 0.f, acc1 = 0.f;

        // ---- raw-radian MUFU waves: 3 FFMA + 1 MUFU per point per wave ----
#pragma unroll 4
        for (int i = 0; i < RAWN; i++) {
            float4 q = swp[i];
            float u0 = fmaf(x0, q.x, fmaf(y0, q.y, q.z));
            float u1 = fmaf(x1, q.x, fmaf(y1, q.y, q.z));
            acc0 = fmaf(q.w, sinap(u0), acc0);
            acc1 = fmaf(q.w, sinap(u1), acc1);
        }

        // ---- poly waves: exact half-cycle reduction, A-folded coeffs ----
#pragma unroll
        for (int i = 0; i < POLYN; i++) {
            float4 q = swp[RAWN + i];
            float4 c = spoly[i];
            {
                float v = fmaf(x0, q.x, fmaf(y0, q.y, q.z));  // half-cycles
                float t = v + MAGF;              // mantissa bit0 = parity of rint(v)
                float nn = t - MAGF;             // rint(v)
                float d = v - nn;                // [-0.5, 0.5]
                d = __uint_as_float(__float_as_uint(d) ^ (__float_as_uint(t) << 31));
                float s = d * d;                 // sign-invariant
                float pp = fmaf(c.w, s, c.z);
                pp = fmaf(pp, s, c.y);
                pp = fmaf(pp, s, c.x);           // A * poly(s)
                acc0 = fmaf(pp, d, acc0);        // A * sin(pi*d), signed
            }
            {
                float v = fmaf(x1, q.x, fmaf(y1, q.y, q.z));
                float t = v + MAGF;
                float nn = t - MAGF;
                float d = v - nn;
                d = __uint_as_float(__float_as_uint(d) ^ (__float_as_uint(t) << 31));
                float s = d * d;
                float pp = fmaf(c.w, s, c.z);
                pp = fmaf(pp, s, c.y);
                pp = fmaf(pp, s, c.x);
                acc1 = fmaf(pp, d, acc1);
            }
        }

        out2[p] = make_float2(acc0, acc1);
    }

    // Odd-n tail: single scalar point.
    if ((n & 1) && blockIdx.x == 0 && threadIdx.x == 0) {
        float tx = ((const float2*)x4)[n - 1].x;
        float ty = ((const float2*)x4)[n - 1].y;
        float ac = 0.f;
        for (int i = 0; i < RAWN; i++) {
            float4 q = swp[i];
            float u = fmaf(tx, q.x, fmaf(ty, q.y, q.z));
            ac = fmaf(q.w, sinap(u), ac);
        }
        for (int i = 0; i < POLYN; i++) {
            float4 q = swp[RAWN + i];
            float4 c = spoly[i];
            float v = fmaf(tx, q.x, fmaf(ty, q.y, q.z));
            float nn = rintf(v);
            float d = v - nn;
            if (((int)nn) & 1) d = -d;
            float s = d * d;
            float pp = fmaf(c.w, s, c.z);
            pp = fmaf(pp, s, c.y);
            pp = fmaf(pp, s, c.x);
            ac = fmaf(pp, d, ac);
        }
        ((float*)out2)[n - 1] = ac;
    }
}

extern "C" void kernel_launch(void* const* d_in, const int* in_sizes, int n_in,
                              void* d_out, int out_size) {
    const float* x      = (const float*)d_in[0];  // [N,2]
    const float* freqs  = (const float*)d_in[1];  // [W,1]
    const float* rots   = (const float*)d_in[2];  // [W,1]
    const float* coeffs = (const float*)d_in[3];  // [W,2]
    float* out = (float*)d_out;                   // [N,1]

    int n = in_sizes[0] / 2;

    wave_kernel<<<GRID_X, TPB>>>((const float4*)x, freqs, rots, coeffs,
                                 (float2*)out, n);
}

// round 14
// speedup vs baseline: 1.6322x; 1.6322x over previous
#include <cuda_runtime.h>
#include <cuda_bf16.h>

#define N_WAVES 128
#define TPB 128
#define PPT 4            // points per thread = 2 float4 loads

__device__ __forceinline__ float sinap(float a) {
    float r; asm("sin.approx.f32 %0, %1;" : "=f"(r) : "f"(a)); return r;
}

__global__ void __launch_bounds__(TPB, 8)
wave_kernel(const float4* __restrict__ x4,   // 2 points per float4
            const float* __restrict__ freqs,
            const float* __restrict__ rots,
            const float* __restrict__ coeffs,
            float2* __restrict__ out2, int n) {
    // All waves on the raw-radian MUFU path: swp[w] = (gx, gy, ph, A), radians.
    // 3 FFMA + 1 MUFU per point per wave — the FMA-op minimum for this problem.
    __shared__ float4 swp[N_WAVES];
    if (threadIdx.x < N_WAVES) {
        int w = threadIdx.x;
        float f  = freqs[w];
        float r  = rots[w];
        float c0 = coeffs[2 * w];
        float c1 = coeffs[2 * w + 1];
        float sr, cr;
        sincosf(r, &sr, &cr);
        float A  = sqrtf(c0 * c0 + c1 * c1);
        float ph = atan2f(c1, c0);                 // radians
        const float two_pi = 6.283185307179586f;
        swp[w] = make_float4(two_pi * f * cr, two_pi * f * sr, ph, A);
    }
    __syncthreads();

    int pairsTotal = n >> 1;
    int pA = blockIdx.x * (2 * TPB) + threadIdx.x;   // float4 index, pair 1
    int pB = pA + TPB;                               // float4 index, pair 2

    float4 a = (pA < pairsTotal) ? x4[pA] : make_float4(0.f, 0.f, 0.f, 0.f);
    float4 b = (pB < pairsTotal) ? x4[pB] : make_float4(0.f, 0.f, 0.f, 0.f);
    float x0 = a.x, y0 = a.y, x1 = a.z, y1 = a.w;
    float x2 = b.x, y2 = b.y, x3 = b.z, y3 = b.w;
    float acc0 = 0.f, acc1 = 0.f, acc2 = 0.f, acc3 = 0.f;

#pragma unroll 4
    for (int i = 0; i < N_WAVES; i++) {
        float4 q = swp[i];   // LDS.128 broadcast, amortized over 4 points
        float u0 = fmaf(x0, q.x, fmaf(y0, q.y, q.z));
        float u1 = fmaf(x1, q.x, fmaf(y1, q.y, q.z));
        float u2 = fmaf(x2, q.x, fmaf(y2, q.y, q.z));
        float u3 = fmaf(x3, q.x, fmaf(y3, q.y, q.z));
        acc0 = fmaf(q.w, sinap(u0), acc0);
        acc1 = fmaf(q.w, sinap(u1), acc1);
        acc2 = fmaf(q.w, sinap(u2), acc2);
        acc3 = fmaf(q.w, sinap(u3), acc3);
    }

    if (pA < pairsTotal) out2[pA] = make_float2(acc0, acc1);
    if (pB < pairsTotal) out2[pB] = make_float2(acc2, acc3);

    // Odd-n tail: single scalar point.
    if ((n & 1) && blockIdx.x == 0 && threadIdx.x == 0) {
        float tx = ((const float2*)x4)[n - 1].x;
        float ty = ((const float2*)x4)[n - 1].y;
        float ac = 0.f;
        for (int i = 0; i < N_WAVES; i++) {
            float4 q = swp[i];
            float u = fmaf(tx, q.x, fmaf(ty, q.y, q.z));
            ac = fmaf(q.w, sinap(u), ac);
        }
        ((float*)out2)[n - 1] = ac;
    }
}

extern "C" void kernel_launch(void* const* d_in, const int* in_sizes, int n_in,
                              void* d_out, int out_size) {
    const float* x      = (const float*)d_in[0];  // [N,2]
    const float* freqs  = (const float*)d_in[1];  // [W,1]
    const float* rots   = (const float*)d_in[2];  // [W,1]
    const float* coeffs = (const float*)d_in[3];  // [W,2]
    float* out = (float*)d_out;                   // [N,1]

    int n = in_sizes[0] / 2;

    int pairs = (n + 1) / 2;
    int blocks = (pairs + 2 * TPB - 1) / (2 * TPB);
    wave_kernel<<<blocks, TPB>>>((const float4*)x, freqs, rots, coeffs,
                                 (float2*)out, n);
}

// round 15
// speedup vs baseline: 1.6642x; 1.0196x over previous
#include <cuda_runtime.h>
#include <cuda_bf16.h>

#define N_WAVES 128
#define TPB 128

__device__ __forceinline__ float sinap(float a) {
    float r; asm("sin.approx.f32 %0, %1;" : "=f"(r) : "f"(a)); return r;
}

__global__ void __launch_bounds__(TPB, 12)
wave_kernel(const float4* __restrict__ x4,   // 2 points per float4
            const float* __restrict__ freqs,
            const float* __restrict__ rots,
            const float* __restrict__ coeffs,
            float2* __restrict__ out2, int n) {
    // All waves on the raw-radian MUFU path: swp[w] = (gx, gy, ph, A), radians.
    // 3 FFMA + 1 MUFU per point per wave — the FFMA floor for this problem.
    __shared__ float4 swp[N_WAVES];
    if (threadIdx.x < N_WAVES) {
        int w = threadIdx.x;
        float f  = freqs[w];
        float r  = rots[w];
        float c0 = coeffs[2 * w];
        float c1 = coeffs[2 * w + 1];
        float sr, cr;
        sincosf(r, &sr, &cr);
        float A  = sqrtf(c0 * c0 + c1 * c1);
        float ph = atan2f(c1, c0);                 // radians
        const float two_pi = 6.283185307179586f;
        swp[w] = make_float4(two_pi * f * cr, two_pi * f * sr, ph, A);
    }
    __syncthreads();

    int pairsTotal = n >> 1;                      // number of float4s
    int p = blockIdx.x * TPB + threadIdx.x;       // one float4 per thread

    float4 a = (p < pairsTotal) ? x4[p] : make_float4(0.f, 0.f, 0.f, 0.f);
    float x0 = a.x, y0 = a.y, x1 = a.z, y1 = a.w;
    float acc0 = 0.f, acc1 = 0.f;

#pragma unroll 4
    for (int i = 0; i < N_WAVES; i++) {
        float4 q = swp[i];   // LDS.128 broadcast, conflict-free
        float u0 = fmaf(x0, q.x, fmaf(y0, q.y, q.z));
        float u1 = fmaf(x1, q.x, fmaf(y1, q.y, q.z));
        acc0 = fmaf(q.w, sinap(u0), acc0);
        acc1 = fmaf(q.w, sinap(u1), acc1);
    }

    if (p < pairsTotal) out2[p] = make_float2(acc0, acc1);

    // Odd-n tail: single scalar point.
    if ((n & 1) && blockIdx.x == 0 && threadIdx.x == 0) {
        float tx = ((const float2*)x4)[n - 1].x;
        float ty = ((const float2*)x4)[n - 1].y;
        float ac = 0.f;
        for (int i = 0; i < N_WAVES; i++) {
            float4 q = swp[i];
            float u = fmaf(tx, q.x, fmaf(ty, q.y, q.z));
            ac = fmaf(q.w, sinap(u), ac);
        }
        ((float*)out2)[n - 1] = ac;
    }
}

extern "C" void kernel_launch(void* const* d_in, const int* in_sizes, int n_in,
                              void* d_out, int out_size) {
    const float* x      = (const float*)d_in[0];  // [N,2]
    const float* freqs  = (const float*)d_in[1];  // [W,1]
    const float* rots   = (const float*)d_in[2];  // [W,1]
    const float* coeffs = (const float*)d_in[3];  // [W,2]
    float* out = (float*)d_out;                   // [N,1]

    int n = in_sizes[0] / 2;

    int pairs = (n + 1) / 2;                       // float4 count
    int blocks = (pairs + TPB - 1) / TPB;
    wave_kernel<<<blocks, TPB>>>((const float4*)x, freqs, rots, coeffs,
                                 (float2*)out, n);
}